// round 7
// baseline (speedup 1.0000x reference)
#include <cuda_runtime.h>
#include <cuda_fp16.h>
#include <cstdint>

#define D_DIM 1024
#define M_DIM 1024
#define N_MAX 16384

#define BM 128
#define BN 128
#define BK 64                       // halves per k-tile = 128 bytes/row
#define STAGES 3
#define KT_PER_UNIT 24              // split-K: half of the 48 k-tiles
#define NTILE_COLS (M_DIM / BN)     // 8

#define STAGE_BYTES (BM * 128 + BN * 128)   // 32 KB (A then B)
#define SMEM_DYN_BYTES (STAGES * STAGE_BYTES)

// ---------------- static device scratch (no allocation allowed) -------------
__device__ __align__(16) float  g_p2[M_DIM];
__device__ __align__(16) __half g_qhi[(size_t)N_MAX * D_DIM];
__device__ __align__(16) __half g_qlo[(size_t)N_MAX * D_DIM];
__device__ __align__(16) __half g_phi[(size_t)M_DIM * D_DIM];
__device__ __align__(16) __half g_plo[(size_t)M_DIM * D_DIM];
__device__ __align__(16) float  g_qp2[(size_t)N_MAX * M_DIM];   // split-K half 1

// ---------------- helpers ----------------------------------------------------
__device__ __forceinline__ uint32_t smem_to_u32(const void* p) {
    uint32_t a;
    asm("{ .reg .u64 t; cvta.to.shared.u64 t, %1; cvt.u32.u64 %0, t; }" : "=r"(a) : "l"(p));
    return a;
}

__device__ __forceinline__ void cp_async16(uint32_t dst, const void* src) {
    asm volatile("cp.async.cg.shared.global [%0], [%1], 16;" :: "r"(dst), "l"(src) : "memory");
}
#define CP_COMMIT() asm volatile("cp.async.commit_group;" ::: "memory")
#define CP_WAIT(n)  asm volatile("cp.async.wait_group %0;" :: "n"(n) : "memory")

__device__ __forceinline__ void ldsm_x4(uint32_t* r, uint32_t addr) {
    asm volatile("ldmatrix.sync.aligned.m8n8.x4.shared.b16 {%0,%1,%2,%3}, [%4];"
                 : "=r"(r[0]), "=r"(r[1]), "=r"(r[2]), "=r"(r[3]) : "r"(addr));
}

__device__ __forceinline__ void mma16816(float* c, const uint32_t* a, const uint32_t* b) {
    asm volatile(
        "mma.sync.aligned.m16n8k16.row.col.f32.f16.f16.f32 "
        "{%0,%1,%2,%3}, {%4,%5,%6,%7}, {%8,%9}, {%0,%1,%2,%3};"
        : "+f"(c[0]), "+f"(c[1]), "+f"(c[2]), "+f"(c[3])
        : "r"(a[0]), "r"(a[1]), "r"(a[2]), "r"(a[3]), "r"(b[0]), "r"(b[1]));
}

// ---------------------------------------------------------------------------
// Kernel A: split fp32 -> (hi, lo) fp16 pairs for Q and P; fused p2 for P.
// Warp per row (MLP=8), 8 rows per 256-thread block.
// ---------------------------------------------------------------------------
__global__ __launch_bounds__(256) void convert_kernel(const float* __restrict__ q,
                                                      const float* __restrict__ p, int nq) {
    const int row  = blockIdx.x * 8 + (threadIdx.x >> 5);
    const int lane = threadIdx.x & 31;
    const bool isQ = row < nq;
    const float* src = isQ ? (q + (size_t)row * D_DIM) : (p + (size_t)(row - nq) * D_DIM);
    __half* dhi = isQ ? (g_qhi + (size_t)row * D_DIM) : (g_phi + (size_t)(row - nq) * D_DIM);
    __half* dlo = isQ ? (g_qlo + (size_t)row * D_DIM) : (g_plo + (size_t)(row - nq) * D_DIM);

    float4 v[8];
    #pragma unroll
    for (int j = 0; j < 8; j++)
        v[j] = reinterpret_cast<const float4*>(src)[lane + 32 * j];

    #pragma unroll
    for (int j = 0; j < 8; j++) {
        __half h0 = __float2half_rn(v[j].x), h1 = __float2half_rn(v[j].y);
        __half h2 = __float2half_rn(v[j].z), h3 = __float2half_rn(v[j].w);
        __half l0 = __float2half_rn(v[j].x - __half2float(h0));
        __half l1 = __float2half_rn(v[j].y - __half2float(h1));
        __half l2 = __float2half_rn(v[j].z - __half2float(h2));
        __half l3 = __float2half_rn(v[j].w - __half2float(h3));
        __half2 hv[2] = {__halves2half2(h0, h1), __halves2half2(h2, h3)};
        __half2 lv[2] = {__halves2half2(l0, l1), __halves2half2(l2, l3)};
        reinterpret_cast<uint2*>(dhi)[lane + 32 * j] = *reinterpret_cast<uint2*>(hv);
        reinterpret_cast<uint2*>(dlo)[lane + 32 * j] = *reinterpret_cast<uint2*>(lv);
    }

    if (!isQ) {                                 // fused p2 (exact fp32)
        float s = 0.0f;
        #pragma unroll
        for (int j = 0; j < 8; j++)
            s += v[j].x * v[j].x + v[j].y * v[j].y + v[j].z * v[j].z + v[j].w * v[j].w;
        #pragma unroll
        for (int o = 16; o; o >>= 1) s += __shfl_xor_sync(0xffffffffu, s, o);
        if (lane == 0) g_p2[row - nq] = s;
    }
}

// ---------------------------------------------------------------------------
// Kernel B: persistent HMMA GEMM, deterministic split-K=2.
// Work unit u = (tile, half): tile = u>>1, h = u&1; h covers k-tiles
// [24h, 24h+24). h0 accumulates into out, h1 into g_qp2.
// Continuous cp.async pipeline across unit boundaries (stage = seq%3).
// ---------------------------------------------------------------------------
struct LoadSlots { uint32_t dst[4]; int src[4]; };

__device__ __forceinline__ void load_seq(int seq, int bid, int G, uint32_t smem0,
                                         const LoadSlots& ls) {
    const int unit = bid + (seq / KT_PER_UNIT) * G;
    const int kt   = (unit & 1) * KT_PER_UNIT + seq % KT_PER_UNIT;  // global k-tile 0..47
    const int tile = unit >> 1;
    const int p    = kt >> 4;            // pass 0,1,2
    const int k    = kt & 15;
    const __half* A = (p == 2 ? g_qlo : g_qhi)
                      + (size_t)((tile >> 3) * BM) * D_DIM + k * BK;
    const __half* B = (p == 1 ? g_plo : g_phi)
                      + (size_t)((tile & 7) * BN) * D_DIM + k * BK;
    const uint32_t sa = smem0 + (seq % STAGES) * STAGE_BYTES;
    const uint32_t sb = sa + BM * 128;
    #pragma unroll
    for (int i = 0; i < 4; i++) cp_async16(sa + ls.dst[i], A + ls.src[i]);
    #pragma unroll
    for (int i = 0; i < 4; i++) cp_async16(sb + ls.dst[i], B + ls.src[i]);
}

__global__ __launch_bounds__(256, 2) void gemm_kernel(float* __restrict__ out, int n_units) {
    extern __shared__ __align__(128) char dsm[];
    const int tid  = threadIdx.x;
    const int lane = tid & 31;
    const int wid  = tid >> 5;
    const int wm   = wid & 1;
    const int wn   = wid >> 1;
    const int bid  = blockIdx.x;
    const int G    = gridDim.x;

    const uint32_t smem0 = smem_to_u32(dsm);

    LoadSlots ls;
    #pragma unroll
    for (int i = 0; i < 4; i++) {
        int idx = i * 256 + tid, r = idx >> 3, c = idx & 7;
        uint32_t off = (uint32_t)(r * 128 + c * 16);
        ls.dst[i] = off ^ ((off >> 3) & 0x70);
        ls.src[i] = r * D_DIM + c * 8;
    }

    // ldmatrix per-thread addressing (XOR-swizzled 128B rows).
    const int a_row  = wm * 64 + (lane & 15);
    const uint32_t a_base = (uint32_t)(a_row * 128);
    const uint32_t a_xor  = (uint32_t)((a_row & 7) << 4);
    const uint32_t a_sel  = (lane & 16) ? 16u : 0u;
    const int b_row  = wn * 32 + (lane & 7) + ((lane & 16) ? 8 : 0);
    const uint32_t b_base = (uint32_t)(BM * 128 + b_row * 128);
    const uint32_t b_xor  = (uint32_t)((b_row & 7) << 4);
    const uint32_t b_sel  = (lane & 8) ? 16u : 0u;

    const int my_units = (bid < n_units) ? (n_units - bid + G - 1) / G : 0;
    const int my_total = my_units * KT_PER_UNIT;
    if (my_total == 0) return;

    load_seq(0, bid, G, smem0, ls); CP_COMMIT();
    if (my_total > 1) { load_seq(1, bid, G, smem0, ls); }
    CP_COMMIT();

    int seq = 0;
    for (int ui = 0; ui < my_units; ui++) {
        const int unit = bid + ui * G;
        const int tile = unit >> 1;
        const int brow = (tile >> 3) * BM;
        const int bcol = (tile & 7) * BN;
        float* dst = (unit & 1) ? g_qp2 : out;

        float acc[4][4][4];
        #pragma unroll
        for (int i = 0; i < 4; i++)
            #pragma unroll
            for (int j = 0; j < 4; j++)
                #pragma unroll
                for (int k = 0; k < 4; k++) acc[i][j][k] = 0.0f;

        for (int t = 0; t < KT_PER_UNIT; t++, seq++) {
            CP_WAIT(1);
            __syncthreads();
            if (seq + 2 < my_total) load_seq(seq + 2, bid, G, smem0, ls);
            CP_COMMIT();

            const uint32_t sbase = smem0 + (seq % STAGES) * STAGE_BYTES;
            #pragma unroll
            for (int ks = 0; ks < BK / 16; ks++) {
                uint32_t af[4][4], bf[2][4];
                #pragma unroll
                for (int mi = 0; mi < 4; mi++)
                    ldsm_x4(af[mi], sbase + a_base + mi * 16 * 128 +
                                    ((ks * 32 + a_sel) ^ a_xor));
                #pragma unroll
                for (int ni = 0; ni < 2; ni++)
                    ldsm_x4(bf[ni], sbase + b_base + ni * 16 * 128 +
                                    ((ks * 32 + b_sel) ^ b_xor));
                #pragma unroll
                for (int mi = 0; mi < 4; mi++)
                    #pragma unroll
                    for (int nj = 0; nj < 4; nj++)
                        mma16816(acc[mi][nj], af[mi], &bf[nj >> 1][(nj & 1) * 2]);
            }
        }

        // Epilogue — overlaps the already-issued loads of the next unit.
        #pragma unroll
        for (int mi = 0; mi < 4; mi++) {
            #pragma unroll
            for (int nj = 0; nj < 4; nj++) {
                const int r = brow + wm * 64 + mi * 16 + (lane >> 2);
                const int c = bcol + wn * 32 + nj * 8 + (lane & 3) * 2;
                float* o0 = dst + (size_t)r * M_DIM + c;
                float* o1 = dst + (size_t)(r + 8) * M_DIM + c;
                *reinterpret_cast<float2*>(o0) = make_float2(acc[mi][nj][0], acc[mi][nj][1]);
                *reinterpret_cast<float2*>(o1) = make_float2(acc[mi][nj][2], acc[mi][nj][3]);
            }
        }
    }
}

// ---------------------------------------------------------------------------
// Kernel C: in-place row softmax of s[m] = 2*(qp0+qp1)[n,m] - p2[m].
// Warp per row; deterministic fp32 (fixed addition order).
// ---------------------------------------------------------------------------
__global__ __launch_bounds__(256) void softmax_kernel(float* __restrict__ out) {
    const int warp = threadIdx.x >> 5, lane = threadIdx.x & 31;
    const int row  = blockIdx.x * 8 + warp;
    float4* p = reinterpret_cast<float4*>(out + (size_t)row * M_DIM);
    const float4* p1 = reinterpret_cast<const float4*>(g_qp2 + (size_t)row * M_DIM);
    const float4* pp = reinterpret_cast<const float4*>(g_p2);

    float s[32];
    #pragma unroll
    for (int j = 0; j < 8; j++) {
        float4 a = __ldcg(&p[lane + 32 * j]);       // L2-hot after GEMM
        float4 b = __ldcg(&p1[lane + 32 * j]);
        float4 q = pp[lane + 32 * j];
        s[4 * j + 0] = 2.0f * (a.x + b.x) - q.x;
        s[4 * j + 1] = 2.0f * (a.y + b.y) - q.y;
        s[4 * j + 2] = 2.0f * (a.z + b.z) - q.z;
        s[4 * j + 3] = 2.0f * (a.w + b.w) - q.w;
    }

    float m = s[0];
    #pragma unroll
    for (int i = 1; i < 32; i++) m = fmaxf(m, s[i]);
    #pragma unroll
    for (int o = 16; o; o >>= 1) m = fmaxf(m, __shfl_xor_sync(0xffffffffu, m, o));

    float sum = 0.0f;
    #pragma unroll
    for (int i = 0; i < 32; i++) {
        s[i] = __expf(s[i] - m);
        sum += s[i];
    }
    #pragma unroll
    for (int o = 16; o; o >>= 1) sum += __shfl_xor_sync(0xffffffffu, sum, o);
    const float inv = 1.0f / sum;

    #pragma unroll
    for (int j = 0; j < 8; j++)
        p[lane + 32 * j] = make_float4(s[4 * j + 0] * inv, s[4 * j + 1] * inv,
                                       s[4 * j + 2] * inv, s[4 * j + 3] * inv);
}

// ---------------------------------------------------------------------------
extern "C" void kernel_launch(void* const* d_in, const int* in_sizes, int n_in,
                              void* d_out, int out_size) {
    const float* query = (const float*)d_in[0];   // [N, 1024] fp32
    const float* proto = (const float*)d_in[1];   // [1024, 1024] fp32
    float* out = (float*)d_out;                   // [N, 1024] fp32
    const int N = in_sizes[0] / D_DIM;

    cudaFuncSetAttribute(gemm_kernel, cudaFuncAttributeMaxDynamicSharedMemorySize,
                         SMEM_DYN_BYTES);

    int sm_count = 148;
    cudaDeviceGetAttribute(&sm_count, cudaDevAttrMultiProcessorCount, 0);
    const int n_units = (N / BM) * NTILE_COLS * 2;  // 2048 split-K work units
    int grid = 2 * sm_count;                        // fills 2-CTA/SM residency
    if (grid > n_units) grid = n_units;

    convert_kernel<<<(N + M_DIM) / 8, 256>>>(query, proto, N);

    gemm_kernel<<<grid, 256, SMEM_DYN_BYTES>>>(out, n_units);

    softmax_kernel<<<N / 8, 256>>>(out);
}

// round 8
// speedup vs baseline: 1.0977x; 1.0977x over previous
#include <cuda_runtime.h>
#include <cuda_fp16.h>
#include <cstdint>

#define D_DIM 1024
#define M_DIM 1024
#define N_MAX 16384

#define BM 128
#define BN 128
#define BK 64                       // halves per k-tile = 128 bytes/row
#define STAGES 3
#define NPASS 3
#define TOT_TILES (NPASS * (D_DIM / BK))    // 48

#define STAGE_BYTES (BM * 128 + BN * 128)   // 32 KB (A then B)
#define SMEM_DYN_BYTES (STAGES * STAGE_BYTES)

// ---------------- static device scratch (no allocation allowed) -------------
__device__ __align__(16) float  g_p2[M_DIM];
__device__ __align__(16) __half g_qhi[(size_t)N_MAX * D_DIM];
__device__ __align__(16) __half g_qlo[(size_t)N_MAX * D_DIM];
__device__ __align__(16) __half g_phi[(size_t)M_DIM * D_DIM];
__device__ __align__(16) __half g_plo[(size_t)M_DIM * D_DIM];

// ---------------- helpers ----------------------------------------------------
__device__ __forceinline__ uint32_t smem_to_u32(const void* p) {
    uint32_t a;
    asm("{ .reg .u64 t; cvta.to.shared.u64 t, %1; cvt.u32.u64 %0, t; }" : "=r"(a) : "l"(p));
    return a;
}

__device__ __forceinline__ void cp_async16(uint32_t dst, const void* src) {
    asm volatile("cp.async.cg.shared.global [%0], [%1], 16;" :: "r"(dst), "l"(src) : "memory");
}
#define CP_COMMIT() asm volatile("cp.async.commit_group;" ::: "memory")
#define CP_WAIT(n)  asm volatile("cp.async.wait_group %0;" :: "n"(n) : "memory")

__device__ __forceinline__ void ldsm_x4(uint32_t* r, uint32_t addr) {
    asm volatile("ldmatrix.sync.aligned.m8n8.x4.shared.b16 {%0,%1,%2,%3}, [%4];"
                 : "=r"(r[0]), "=r"(r[1]), "=r"(r[2]), "=r"(r[3]) : "r"(addr));
}

__device__ __forceinline__ void mma16816(float* c, const uint32_t* a, const uint32_t* b) {
    asm volatile(
        "mma.sync.aligned.m16n8k16.row.col.f32.f16.f16.f32 "
        "{%0,%1,%2,%3}, {%4,%5,%6,%7}, {%8,%9}, {%0,%1,%2,%3};"
        : "+f"(c[0]), "+f"(c[1]), "+f"(c[2]), "+f"(c[3])
        : "r"(a[0]), "r"(a[1]), "r"(a[2]), "r"(a[3]), "r"(b[0]), "r"(b[1]));
}

// ---------------------------------------------------------------------------
// Kernel A: split fp32 -> (hi, lo) fp16 pairs for Q and P; fused p2 for P.
// Warp per row (MLP=8), 8 rows per 256-thread block.
// ---------------------------------------------------------------------------
__global__ __launch_bounds__(256) void convert_kernel(const float* __restrict__ q,
                                                      const float* __restrict__ p, int nq) {
    const int row  = blockIdx.x * 8 + (threadIdx.x >> 5);
    const int lane = threadIdx.x & 31;
    const bool isQ = row < nq;
    const float* src = isQ ? (q + (size_t)row * D_DIM) : (p + (size_t)(row - nq) * D_DIM);
    __half* dhi = isQ ? (g_qhi + (size_t)row * D_DIM) : (g_phi + (size_t)(row - nq) * D_DIM);
    __half* dlo = isQ ? (g_qlo + (size_t)row * D_DIM) : (g_plo + (size_t)(row - nq) * D_DIM);

    float4 v[8];
    #pragma unroll
    for (int j = 0; j < 8; j++)
        v[j] = reinterpret_cast<const float4*>(src)[lane + 32 * j];

    #pragma unroll
    for (int j = 0; j < 8; j++) {
        __half h0 = __float2half_rn(v[j].x), h1 = __float2half_rn(v[j].y);
        __half h2 = __float2half_rn(v[j].z), h3 = __float2half_rn(v[j].w);
        __half l0 = __float2half_rn(v[j].x - __half2float(h0));
        __half l1 = __float2half_rn(v[j].y - __half2float(h1));
        __half l2 = __float2half_rn(v[j].z - __half2float(h2));
        __half l3 = __float2half_rn(v[j].w - __half2float(h3));
        __half2 hv[2] = {__halves2half2(h0, h1), __halves2half2(h2, h3)};
        __half2 lv[2] = {__halves2half2(l0, l1), __halves2half2(l2, l3)};
        reinterpret_cast<uint2*>(dhi)[lane + 32 * j] = *reinterpret_cast<uint2*>(hv);
        reinterpret_cast<uint2*>(dlo)[lane + 32 * j] = *reinterpret_cast<uint2*>(lv);
    }

    if (!isQ) {                                 // fused p2 (exact fp32)
        float s = 0.0f;
        #pragma unroll
        for (int j = 0; j < 8; j++)
            s += v[j].x * v[j].x + v[j].y * v[j].y + v[j].z * v[j].z + v[j].w * v[j].w;
        #pragma unroll
        for (int o = 16; o; o >>= 1) s += __shfl_xor_sync(0xffffffffu, s, o);
        if (lane == 0) g_p2[row - nq] = s;
    }
}

// ---------------------------------------------------------------------------
// Kernel B: HMMA GEMM (round-4 proven config, 290us).
// qp = Qhi*Phi^T + Qhi*Plo^T + Qlo*Phi^T -> out
// 128x128 CTA tile, BK=64, 3-stage cp.async pipeline, one barrier per k-tile.
// ---------------------------------------------------------------------------
struct LoadSlots { uint32_t dst[4]; int src[4]; };

__device__ __forceinline__ void load_tile(int t, uint32_t smem0,
                                          const __half* const* passA,
                                          const __half* const* passB,
                                          const LoadSlots& ls) {
    const int stage = t % STAGES;
    const __half* A = passA[t >> 4] + (t & 15) * BK;
    const __half* B = passB[t >> 4] + (t & 15) * BK;
    const uint32_t sa = smem0 + stage * STAGE_BYTES;
    const uint32_t sb = sa + BM * 128;
    #pragma unroll
    for (int i = 0; i < 4; i++) cp_async16(sa + ls.dst[i], A + ls.src[i]);
    #pragma unroll
    for (int i = 0; i < 4; i++) cp_async16(sb + ls.dst[i], B + ls.src[i]);
}

__global__ __launch_bounds__(256, 2) void gemm_kernel(float* __restrict__ out) {
    extern __shared__ __align__(128) char dsm[];
    const int tid  = threadIdx.x;
    const int lane = tid & 31;
    const int wid  = tid >> 5;
    const int wm   = wid & 1;       // 2 warps along M
    const int wn   = wid >> 1;      // 4 warps along N
    const int brow = blockIdx.y * BM;
    const int bcol = blockIdx.x * BN;

    const uint32_t smem0 = smem_to_u32(dsm);

    LoadSlots ls;
    #pragma unroll
    for (int i = 0; i < 4; i++) {
        int idx = i * 256 + tid, r = idx >> 3, c = idx & 7;
        uint32_t off = (uint32_t)(r * 128 + c * 16);
        ls.dst[i] = off ^ ((off >> 3) & 0x70);
        ls.src[i] = r * D_DIM + c * 8;
    }

    const __half* passA[NPASS] = {g_qhi + (size_t)brow * D_DIM,
                                  g_qhi + (size_t)brow * D_DIM,
                                  g_qlo + (size_t)brow * D_DIM};
    const __half* passB[NPASS] = {g_phi + (size_t)bcol * D_DIM,
                                  g_plo + (size_t)bcol * D_DIM,
                                  g_phi + (size_t)bcol * D_DIM};

    // ldmatrix per-thread addressing (XOR-swizzled 128B rows).
    const int a_row  = wm * 64 + (lane & 15);
    const uint32_t a_base = (uint32_t)(a_row * 128);
    const uint32_t a_xor  = (uint32_t)((a_row & 7) << 4);
    const uint32_t a_sel  = (lane & 16) ? 16u : 0u;
    const int b_row  = wn * 32 + (lane & 7) + ((lane & 16) ? 8 : 0);
    const uint32_t b_base = (uint32_t)(BM * 128 + b_row * 128);
    const uint32_t b_xor  = (uint32_t)((b_row & 7) << 4);
    const uint32_t b_sel  = (lane & 8) ? 16u : 0u;

    float acc[4][4][4];
    #pragma unroll
    for (int i = 0; i < 4; i++)
        #pragma unroll
        for (int j = 0; j < 4; j++)
            #pragma unroll
            for (int k = 0; k < 4; k++) acc[i][j][k] = 0.0f;

    #pragma unroll
    for (int t = 0; t < STAGES - 1; t++) {
        load_tile(t, smem0, passA, passB, ls);
        CP_COMMIT();
    }

    for (int t = 0; t < TOT_TILES; t++) {
        CP_WAIT(STAGES - 2);
        __syncthreads();
        if (t + STAGES - 1 < TOT_TILES)
            load_tile(t + STAGES - 1, smem0, passA, passB, ls);
        CP_COMMIT();

        const uint32_t sbase = smem0 + (t % STAGES) * STAGE_BYTES;
        #pragma unroll
        for (int ks = 0; ks < BK / 16; ks++) {
            uint32_t af[4][4], bf[2][4];
            #pragma unroll
            for (int mi = 0; mi < 4; mi++)
                ldsm_x4(af[mi], sbase + a_base + mi * 16 * 128 +
                                ((ks * 32 + a_sel) ^ a_xor));
            #pragma unroll
            for (int ni = 0; ni < 2; ni++)
                ldsm_x4(bf[ni], sbase + b_base + ni * 16 * 128 +
                                ((ks * 32 + b_sel) ^ b_xor));
            #pragma unroll
            for (int mi = 0; mi < 4; mi++)
                #pragma unroll
                for (int nj = 0; nj < 4; nj++)
                    mma16816(acc[mi][nj], af[mi], &bf[nj >> 1][(nj & 1) * 2]);
        }
    }

    // Epilogue: store raw qp (softmax pass applies 2*qp - p2).
    #pragma unroll
    for (int mi = 0; mi < 4; mi++) {
        #pragma unroll
        for (int nj = 0; nj < 4; nj++) {
            const int r = brow + wm * 64 + mi * 16 + (lane >> 2);
            const int c = bcol + wn * 32 + nj * 8 + (lane & 3) * 2;
            float* o0 = out + (size_t)r * M_DIM + c;
            float* o1 = out + (size_t)(r + 8) * M_DIM + c;
            *reinterpret_cast<float2*>(o0) = make_float2(acc[mi][nj][0], acc[mi][nj][1]);
            *reinterpret_cast<float2*>(o1) = make_float2(acc[mi][nj][2], acc[mi][nj][3]);
        }
    }
}

// ---------------------------------------------------------------------------
// Kernel C: in-place row softmax of s[m] = 2*qp[n,m] - p2[m]. Warp per row.
// Online max/sum (low regs -> high occupancy); second __ldcg pass (L2-hot)
// recomputes exp for the write. Deterministic: fixed traversal order.
// ---------------------------------------------------------------------------
__global__ __launch_bounds__(256) void softmax_kernel(float* __restrict__ out) {
    const int warp = threadIdx.x >> 5, lane = threadIdx.x & 31;
    const int row  = blockIdx.x * 8 + warp;
    float4* p = reinterpret_cast<float4*>(out + (size_t)row * M_DIM);
    const float4* pp = reinterpret_cast<const float4*>(g_p2);

    // Pass 1: online max + rescaled sum.
    float m = -3.4e38f, sum = 0.0f;
    #pragma unroll
    for (int j = 0; j < 8; j++) {
        float4 v = __ldcg(&p[lane + 32 * j]);
        float4 q = pp[lane + 32 * j];
        float s0 = 2.0f * v.x - q.x, s1 = 2.0f * v.y - q.y;
        float s2 = 2.0f * v.z - q.z, s3 = 2.0f * v.w - q.w;
        float m4 = fmaxf(fmaxf(s0, s1), fmaxf(s2, s3));
        float mn = fmaxf(m, m4);
        sum = sum * __expf(m - mn)
            + __expf(s0 - mn) + __expf(s1 - mn)
            + __expf(s2 - mn) + __expf(s3 - mn);
        m = mn;
    }
    // Warp-combine (max, sum) pairs.
    #pragma unroll
    for (int o = 16; o; o >>= 1) {
        float mo = __shfl_xor_sync(0xffffffffu, m, o);
        float so = __shfl_xor_sync(0xffffffffu, sum, o);
        float mn = fmaxf(m, mo);
        sum = sum * __expf(m - mn) + so * __expf(mo - mn);
        m = mn;
    }
    const float inv = 1.0f / sum;

    // Pass 2: reload (L2-resident), exp, scale, store.
    #pragma unroll
    for (int j = 0; j < 8; j++) {
        float4 v = __ldcg(&p[lane + 32 * j]);
        float4 q = pp[lane + 32 * j];
        float4 r;
        r.x = __expf(2.0f * v.x - q.x - m) * inv;
        r.y = __expf(2.0f * v.y - q.y - m) * inv;
        r.z = __expf(2.0f * v.z - q.z - m) * inv;
        r.w = __expf(2.0f * v.w - q.w - m) * inv;
        p[lane + 32 * j] = r;
    }
}

// ---------------------------------------------------------------------------
extern "C" void kernel_launch(void* const* d_in, const int* in_sizes, int n_in,
                              void* d_out, int out_size) {
    const float* query = (const float*)d_in[0];   // [N, 1024] fp32
    const float* proto = (const float*)d_in[1];   // [1024, 1024] fp32
    float* out = (float*)d_out;                   // [N, 1024] fp32
    const int N = in_sizes[0] / D_DIM;

    cudaFuncSetAttribute(gemm_kernel, cudaFuncAttributeMaxDynamicSharedMemorySize,
                         SMEM_DYN_BYTES);

    convert_kernel<<<(N + M_DIM) / 8, 256>>>(query, proto, N);

    dim3 grid(M_DIM / BN, N / BM);                // (8, 128)
    gemm_kernel<<<grid, 256, SMEM_DYN_BYTES>>>(out);

    softmax_kernel<<<N / 8, 256>>>(out);
}